// round 3
// baseline (speedup 1.0000x reference)
#include <cuda_runtime.h>
#include <stdint.h>
#include <math.h>

#define HEADS  12
#define DMODEL 768
#define DK     64
#define BATCH  2
#define SLEN   2048
#define MTOT   (BATCH * SLEN)   // 4096

__device__ float g_qh[BATCH * HEADS * SLEN * DK];
__device__ float g_kh[BATCH * HEADS * SLEN * DK];
__device__ float g_vh[BATCH * HEADS * SLEN * DK];
__device__ float g_concat[MTOT * DMODEL];

// ---------------------------------------------------------------------------
__device__ __forceinline__ uint32_t f2tf(float x) {
    uint32_t r;
    asm("cvt.rna.tf32.f32 %0, %1;" : "=r"(r) : "f"(x));
    return r;
}

__device__ __forceinline__ void mma8(float* c,
    uint32_t a0, uint32_t a1, uint32_t a2, uint32_t a3,
    uint32_t b0, uint32_t b1)
{
    asm volatile(
        "mma.sync.aligned.m16n8k8.row.col.f32.tf32.tf32.f32 "
        "{%0,%1,%2,%3},{%4,%5,%6,%7},{%8,%9},{%0,%1,%2,%3};"
        : "+f"(c[0]), "+f"(c[1]), "+f"(c[2]), "+f"(c[3])
        : "r"(a0), "r"(a1), "r"(a2), "r"(a3), "r"(b0), "r"(b1));
}

// Pair-interleave slot: within each 8-wide k chunk, k -> 2*(k&3) + ((k&4)>>2).
// Fragments (k=q, k=q+4) land in adjacent words -> LDS.64.

// ---------------------------------------------------------------------------
// C = A @ W^T + bias with double-buffered smem. Block 128x128, BK=16,
// 8 warps (4m x 2n). blockIdx.z selects (A,C). permute -> [B,H,S,Dk] store.
// ---------------------------------------------------------------------------
#define GST 24                  // row stride in words (16 k + pad)
#define G_BUF (128 * GST)       // words per operand per buffer
#define G_SMEM_BYTES (4 * G_BUF * 4)   // 2 operands x 2 buffers = 49152 B

__global__ __launch_bounds__(256) void gemm_tf32(
    const float* __restrict__ A0, const float* __restrict__ A1,
    const float* __restrict__ A2,
    float* __restrict__ C0, float* __restrict__ C1, float* __restrict__ C2,
    const float* __restrict__ W, const float* __restrict__ bias, int permute)
{
    extern __shared__ uint32_t gsm[];
    uint32_t* As = gsm;               // [2][128*GST]
    uint32_t* Bs = gsm + 2 * G_BUF;   // [2][128*GST]

    const float* A = (blockIdx.z == 0) ? A0 : (blockIdx.z == 1) ? A1 : A2;
    float*       C = (blockIdx.z == 0) ? C0 : (blockIdx.z == 1) ? C1 : C2;

    const int tid  = threadIdx.x;
    const int lane = tid & 31;
    const int wid  = tid >> 5;
    const int g = lane >> 2, q = lane & 3;
    const int wm = wid >> 1, wn = wid & 1;
    const int m0 = blockIdx.y << 7, n0 = blockIdx.x << 7;
    const int lrow = tid >> 2;           // 0..63
    const int lc4  = (tid & 3) << 2;     // 0,4,8,12
    const int s0   = (lc4 & 8) + ((lc4 >> 2) & 1);  // interleave start slot

    float acc[2][8][4];
    #pragma unroll
    for (int im = 0; im < 2; im++)
        #pragma unroll
        for (int j = 0; j < 8; j++)
            #pragma unroll
            for (int t = 0; t < 4; t++) acc[im][j][t] = 0.f;

    float4 pa[2], pw[2];
    #pragma unroll
    for (int p = 0; p < 2; p++) {
        pa[p] = *(const float4*)(A + (size_t)(m0 + lrow + p * 64) * DMODEL + lc4);
        pw[p] = *(const float4*)(W + (size_t)(n0 + lrow + p * 64) * DMODEL + lc4);
    }
    // store prologue tile into buffer 0
    #pragma unroll
    for (int p = 0; p < 2; p++) {
        uint32_t* ar = As + (lrow + p * 64) * GST + s0;
        ar[0] = f2tf(pa[p].x); ar[2] = f2tf(pa[p].y);
        ar[4] = f2tf(pa[p].z); ar[6] = f2tf(pa[p].w);
        uint32_t* br = Bs + (lrow + p * 64) * GST + s0;
        br[0] = f2tf(pw[p].x); br[2] = f2tf(pw[p].y);
        br[4] = f2tf(pw[p].z); br[6] = f2tf(pw[p].w);
    }

    const int NIT = DMODEL / 16;   // 48
    for (int it = 0; it < NIT; it++) {
        __syncthreads();
        if (it + 1 < NIT) {
            const int k0 = (it + 1) << 4;
            #pragma unroll
            for (int p = 0; p < 2; p++) {
                pa[p] = *(const float4*)(A + (size_t)(m0 + lrow + p * 64) * DMODEL + k0 + lc4);
                pw[p] = *(const float4*)(W + (size_t)(n0 + lrow + p * 64) * DMODEL + k0 + lc4);
            }
        }
        const uint32_t* ab = As + (it & 1) * G_BUF;
        const uint32_t* bb = Bs + (it & 1) * G_BUF;
        #pragma unroll
        for (int ks = 0; ks < 2; ks++) {
            const int kb8 = ks * 8 + 2 * q;
            uint2 aA[2][2];
            #pragma unroll
            for (int im = 0; im < 2; im++) {
                const int mr = wm * 32 + im * 16 + g;
                aA[im][0] = *(const uint2*)&ab[mr * GST + kb8];
                aA[im][1] = *(const uint2*)&ab[(mr + 8) * GST + kb8];
            }
            #pragma unroll
            for (int j = 0; j < 8; j++) {
                uint2 bu = *(const uint2*)&bb[(wn * 64 + j * 8 + g) * GST + kb8];
                mma8(acc[0][j], aA[0][0].x, aA[0][1].x, aA[0][0].y, aA[0][1].y, bu.x, bu.y);
                mma8(acc[1][j], aA[1][0].x, aA[1][1].x, aA[1][0].y, aA[1][1].y, bu.x, bu.y);
            }
        }
        if (it + 1 < NIT) {
            uint32_t* aw = As + ((it + 1) & 1) * G_BUF;
            uint32_t* bw = Bs + ((it + 1) & 1) * G_BUF;
            #pragma unroll
            for (int p = 0; p < 2; p++) {
                uint32_t* ar = aw + (lrow + p * 64) * GST + s0;
                ar[0] = f2tf(pa[p].x); ar[2] = f2tf(pa[p].y);
                ar[4] = f2tf(pa[p].z); ar[6] = f2tf(pa[p].w);
                uint32_t* br = bw + (lrow + p * 64) * GST + s0;
                br[0] = f2tf(pw[p].x); br[2] = f2tf(pw[p].y);
                br[4] = f2tf(pw[p].z); br[6] = f2tf(pw[p].w);
            }
        }
    }

    // Epilogue
    #pragma unroll
    for (int im = 0; im < 2; im++) {
        const int row0 = m0 + wm * 32 + im * 16 + g;
        #pragma unroll
        for (int j = 0; j < 8; j++) {
            const int col = n0 + wn * 64 + j * 8 + 2 * q;
            const float b0v = bias[col], b1v = bias[col + 1];
            float2 o0, o1;
            o0.x = acc[im][j][0] + b0v; o0.y = acc[im][j][1] + b1v;
            o1.x = acc[im][j][2] + b0v; o1.y = acc[im][j][3] + b1v;
            if (permute) {
                const int h = col >> 6, d = col & 63;
                const int bi0 = row0 >> 11, sr0 = row0 & (SLEN - 1);
                *(float2*)(C + (((size_t)(bi0 * HEADS + h) * SLEN) + sr0) * DK + d) = o0;
                const int row1 = row0 + 8;
                const int bi1 = row1 >> 11, sr1 = row1 & (SLEN - 1);
                *(float2*)(C + (((size_t)(bi1 * HEADS + h) * SLEN) + sr1) * DK + d) = o1;
            } else {
                *(float2*)(C + (size_t)row0 * DMODEL + col) = o0;
                *(float2*)(C + (size_t)(row0 + 8) * DMODEL + col) = o1;
            }
        }
    }
}

// ---------------------------------------------------------------------------
// Flash attention, tf32 mma, pair-interleaved smem (all frag loads LDS.64).
// Block = 128 q rows of one (b,h); 8 warps x 16 rows; KV tiles of 64.
// ---------------------------------------------------------------------------
#define QST 72
#define OFF_K (128 * QST)          // 9216
#define OFF_V (OFF_K + 64 * QST)   // 13824
#define OFF_P (OFF_V + 4096)       // 17920 (V transposed: 64 d x 8 kchunk x 8)
#define SM_WORDS (OFF_P + 8 * 16 * QST)  // 27136
#define SM_BYTES (SM_WORDS * 4)

__global__ __launch_bounds__(256) void attn_tf32(
    const float* __restrict__ qh, const float* __restrict__ kh,
    const float* __restrict__ vh, float* __restrict__ concat)
{
    extern __shared__ uint32_t sm[];
    uint32_t* Qs = sm;
    uint32_t* Ks = sm + OFF_K;
    uint32_t* Vs = sm + OFF_V;
    uint32_t* Ps = sm + OFF_P;

    const int tid  = threadIdx.x;
    const int lane = tid & 31;
    const int w    = tid >> 5;
    const int g = lane >> 2, q = lane & 3;
    const int qt = blockIdx.x, bh = blockIdx.y;
    const int b = bh / HEADS, h = bh % HEADS;

    const float* Qp = qh + ((size_t)bh * SLEN + qt * 128) * DK;
    const float* Kp = kh + (size_t)bh * SLEN * DK;
    const float* Vp = vh + (size_t)bh * SLEN * DK;

    // Q staged with pair-interleaved k, scaled by 1/8 (= 1/sqrt(Dk), exact)
    #pragma unroll
    for (int p = 0; p < 8; p++) {
        const int idx = tid + p * 256;
        const int row = idx >> 4, c4 = (idx & 15) << 2;
        float4 v = *(const float4*)(Qp + row * DK + c4);
        uint32_t* qr = Qs + row * QST + (c4 & 56) + ((c4 >> 2) & 1);
        qr[0] = f2tf(v.x * 0.125f); qr[2] = f2tf(v.y * 0.125f);
        qr[4] = f2tf(v.z * 0.125f); qr[6] = f2tf(v.w * 0.125f);
    }

    float O[8][4];
    #pragma unroll
    for (int j = 0; j < 8; j++)
        #pragma unroll
        for (int t = 0; t < 4; t++) O[j][t] = 0.f;
    float m0r = -1e30f, m1r = -1e30f, l0r = 0.f, l1r = 0.f;

    uint32_t* Pw = Ps + w * 16 * QST;
    const int mb = w * 16;
    const int ps0 = 2 * ((2 * q) & 3) + ((q & 2) >> 1);  // q:0,1,2,3 -> 0,4,1,5

    for (int kt = 0; kt < SLEN / 64; kt++) {
        __syncthreads();
        const float* kb = Kp + (size_t)kt * 64 * DK;
        const float* vb = Vp + (size_t)kt * 64 * DK;
        #pragma unroll
        for (int p = 0; p < 4; p++) {
            const int idx = tid + p * 256;
            const int row = idx >> 4, c4 = (idx & 15) << 2;
            float4 kv = *(const float4*)(kb + row * DK + c4);
            uint32_t* kr = Ks + row * QST + (c4 & 56) + ((c4 >> 2) & 1);
            kr[0] = f2tf(kv.x); kr[2] = f2tf(kv.y);
            kr[4] = f2tf(kv.z); kr[6] = f2tf(kv.w);
            float4 vv = *(const float4*)(vb + row * DK + c4);
            // V transposed: addr = ((t>>3)*64 + d)*8 + 2*(t&3) + ((t&4)>>2)
            uint32_t* vr = Vs + (((row >> 3) * 64 + c4) << 3)
                              + 2 * (row & 3) + ((row >> 2) & 1);
            vr[0]  = f2tf(vv.x); vr[8]  = f2tf(vv.y);
            vr[16] = f2tf(vv.z); vr[24] = f2tf(vv.w);
        }
        __syncthreads();

        // S = (Q/8) @ K^T
        float S[8][4];
        #pragma unroll
        for (int j = 0; j < 8; j++)
            #pragma unroll
            for (int t = 0; t < 4; t++) S[j][t] = 0.f;
        #pragma unroll
        for (int ks = 0; ks < 8; ks++) {
            const int kb8 = ks * 8 + 2 * q;
            uint2 a0 = *(const uint2*)&Qs[(mb + g) * QST + kb8];
            uint2 a1 = *(const uint2*)&Qs[(mb + g + 8) * QST + kb8];
            #pragma unroll
            for (int j = 0; j < 8; j++) {
                uint2 bu = *(const uint2*)&Ks[(j * 8 + g) * QST + kb8];
                mma8(S[j], a0.x, a1.x, a0.y, a1.y, bu.x, bu.y);
            }
        }

        // Online softmax (rows live on a quad -> shfl xor 1,2)
        float mx0 = -1e30f, mx1 = -1e30f;
        #pragma unroll
        for (int j = 0; j < 8; j++) {
            mx0 = fmaxf(mx0, fmaxf(S[j][0], S[j][1]));
            mx1 = fmaxf(mx1, fmaxf(S[j][2], S[j][3]));
        }
        mx0 = fmaxf(mx0, __shfl_xor_sync(0xffffffffu, mx0, 1));
        mx0 = fmaxf(mx0, __shfl_xor_sync(0xffffffffu, mx0, 2));
        mx1 = fmaxf(mx1, __shfl_xor_sync(0xffffffffu, mx1, 1));
        mx1 = fmaxf(mx1, __shfl_xor_sync(0xffffffffu, mx1, 2));

        const float nm0 = fmaxf(m0r, mx0), nm1 = fmaxf(m1r, mx1);
        const float f0 = __expf(m0r - nm0), f1 = __expf(m1r - nm1);
        m0r = nm0; m1r = nm1;

        float sm0 = 0.f, sm1 = 0.f;
        #pragma unroll
        for (int j = 0; j < 8; j++) {
            const float e0 = __expf(S[j][0] - nm0);
            const float e1 = __expf(S[j][1] - nm0);
            const float e2 = __expf(S[j][2] - nm1);
            const float e3 = __expf(S[j][3] - nm1);
            sm0 += e0 + e1; sm1 += e2 + e3;
            uint32_t* pr = Pw + g * QST + j * 8 + ps0;
            pr[0] = f2tf(e0); pr[2] = f2tf(e1);
            uint32_t* pr2 = Pw + (g + 8) * QST + j * 8 + ps0;
            pr2[0] = f2tf(e2); pr2[2] = f2tf(e3);
        }
        sm0 += __shfl_xor_sync(0xffffffffu, sm0, 1);
        sm0 += __shfl_xor_sync(0xffffffffu, sm0, 2);
        sm1 += __shfl_xor_sync(0xffffffffu, sm1, 1);
        sm1 += __shfl_xor_sync(0xffffffffu, sm1, 2);
        l0r = l0r * f0 + sm0;
        l1r = l1r * f1 + sm1;
        #pragma unroll
        for (int j = 0; j < 8; j++) {
            O[j][0] *= f0; O[j][1] *= f0;
            O[j][2] *= f1; O[j][3] *= f1;
        }
        __syncwarp();

        // O += P @ V
        #pragma unroll
        for (int ks = 0; ks < 8; ks++) {
            const int kb8 = ks * 8 + 2 * q;
            uint2 a0 = *(const uint2*)&Pw[g * QST + kb8];
            uint2 a1 = *(const uint2*)&Pw[(g + 8) * QST + kb8];
            #pragma unroll
            for (int j = 0; j < 8; j++) {
                uint2 bu = *(const uint2*)&Vs[((ks * 64 + j * 8 + g) << 3) + 2 * q];
                mma8(O[j], a0.x, a1.x, a0.y, a1.y, bu.x, bu.y);
            }
        }
    }

    // Normalize + write concat [b][s][h*64+d]
    const float inv0 = 1.f / l0r, inv1 = 1.f / l1r;
    const int srow = qt * 128 + w * 16 + g;
    const size_t base0 = ((size_t)b * SLEN + srow) * DMODEL + h * 64;
    const size_t base1 = base0 + (size_t)8 * DMODEL;
    #pragma unroll
    for (int j = 0; j < 8; j++) {
        float2 o0, o1;
        o0.x = O[j][0] * inv0; o0.y = O[j][1] * inv0;
        o1.x = O[j][2] * inv1; o1.y = O[j][3] * inv1;
        *(float2*)(concat + base0 + j * 8 + 2 * q) = o0;
        *(float2*)(concat + base1 + j * 8 + 2 * q) = o1;
    }
}

// ---------------------------------------------------------------------------
extern "C" void kernel_launch(void* const* d_in, const int* in_sizes, int n_in,
                              void* d_out, int out_size)
{
    (void)in_sizes; (void)n_in; (void)out_size;
    const float* q  = (const float*)d_in[0];
    const float* k  = (const float*)d_in[1];
    const float* v  = (const float*)d_in[2];
    const float* Wk = (const float*)d_in[3];
    const float* bk = (const float*)d_in[4];
    const float* Wo = (const float*)d_in[5];
    const float* bo = (const float*)d_in[6];
    float* out = (float*)d_out;

    float *qh, *kh, *vh, *concat;
    cudaGetSymbolAddress((void**)&qh, g_qh);
    cudaGetSymbolAddress((void**)&kh, g_kh);
    cudaGetSymbolAddress((void**)&vh, g_vh);
    cudaGetSymbolAddress((void**)&concat, g_concat);

    cudaFuncSetAttribute((const void*)gemm_tf32,
                         cudaFuncAttributeMaxDynamicSharedMemorySize, G_SMEM_BYTES);
    cudaFuncSetAttribute((const void*)attn_tf32,
                         cudaFuncAttributeMaxDynamicSharedMemorySize, SM_BYTES);

    // Fused 3-way projection (shared Wk hot in L2)
    dim3 gp(DMODEL / 128, MTOT / 128, 3);   // (6, 32, 3)
    gemm_tf32<<<gp, 256, G_SMEM_BYTES>>>(q, k, v, qh, kh, vh, Wk, bk, 1);

    attn_tf32<<<dim3(SLEN / 128, BATCH * HEADS), 256, SM_BYTES>>>(qh, kh, vh, concat);

    dim3 go(DMODEL / 128, MTOT / 128, 1);
    gemm_tf32<<<go, 256, G_SMEM_BYTES>>>(concat, concat, concat, out, out, out, Wo, bo, 0);
}

// round 6
// speedup vs baseline: 1.2527x; 1.2527x over previous
#include <cuda_runtime.h>
#include <stdint.h>
#include <math.h>

#define HEADS  12
#define DMODEL 768
#define DK     64
#define BATCH  2
#define SLEN   2048
#define MTOT   (BATCH * SLEN)   // 4096

__device__ float g_qh[BATCH * HEADS * SLEN * DK];
__device__ float g_kh[BATCH * HEADS * SLEN * DK];
__device__ float g_vh[BATCH * HEADS * SLEN * DK];
__device__ float g_concat[MTOT * DMODEL];

// ---------------------------------------------------------------------------
__device__ __forceinline__ uint32_t f2tf(float x) {
    uint32_t r;
    asm("cvt.rna.tf32.f32 %0, %1;" : "=r"(r) : "f"(x));
    return r;
}

__device__ __forceinline__ void mma8(float* c,
    uint32_t a0, uint32_t a1, uint32_t a2, uint32_t a3,
    uint32_t b0, uint32_t b1)
{
    asm volatile(
        "mma.sync.aligned.m16n8k8.row.col.f32.tf32.tf32.f32 "
        "{%0,%1,%2,%3},{%4,%5,%6,%7},{%8,%9},{%0,%1,%2,%3};"
        : "+f"(c[0]), "+f"(c[1]), "+f"(c[2]), "+f"(c[3])
        : "r"(a0), "r"(a1), "r"(a2), "r"(a3), "r"(b0), "r"(b1));
}

// ---------------------------------------------------------------------------
// GEMM (R3-proven): C = A @ W^T + bias, double-buffered smem, pair-interleaved
// k layout (LDS.64 frag loads). Block 128x128, BK=16, 8 warps (4m x 2n).
// blockIdx.z selects (A,C). permute -> [B,H,S,Dk] store.
// ---------------------------------------------------------------------------
#define GST 24                  // row stride in words (16 k + pad)
#define G_BUF (128 * GST)       // words per operand per buffer
#define G_SMEM_BYTES (4 * G_BUF * 4)   // 49152 B

__global__ __launch_bounds__(256) void gemm_tf32(
    const float* __restrict__ A0, const float* __restrict__ A1,
    const float* __restrict__ A2,
    float* __restrict__ C0, float* __restrict__ C1, float* __restrict__ C2,
    const float* __restrict__ W, const float* __restrict__ bias, int permute)
{
    extern __shared__ uint32_t gsm[];
    uint32_t* As = gsm;               // [2][128*GST]
    uint32_t* Bs = gsm + 2 * G_BUF;   // [2][128*GST]

    const float* A = (blockIdx.z == 0) ? A0 : (blockIdx.z == 1) ? A1 : A2;
    float*       C = (blockIdx.z == 0) ? C0 : (blockIdx.z == 1) ? C1 : C2;

    const int tid  = threadIdx.x;
    const int lane = tid & 31;
    const int wid  = tid >> 5;
    const int g = lane >> 2, q = lane & 3;
    const int wm = wid >> 1, wn = wid & 1;
    const int m0 = blockIdx.y << 7, n0 = blockIdx.x << 7;
    const int lrow = tid >> 2;           // 0..63
    const int lc4  = (tid & 3) << 2;     // 0,4,8,12
    const int s0   = (lc4 & 8) + ((lc4 >> 2) & 1);  // interleave start slot

    float acc[2][8][4];
    #pragma unroll
    for (int im = 0; im < 2; im++)
        #pragma unroll
        for (int j = 0; j < 8; j++)
            #pragma unroll
            for (int t = 0; t < 4; t++) acc[im][j][t] = 0.f;

    float4 pa[2], pw[2];
    #pragma unroll
    for (int p = 0; p < 2; p++) {
        pa[p] = *(const float4*)(A + (size_t)(m0 + lrow + p * 64) * DMODEL + lc4);
        pw[p] = *(const float4*)(W + (size_t)(n0 + lrow + p * 64) * DMODEL + lc4);
    }
    #pragma unroll
    for (int p = 0; p < 2; p++) {
        uint32_t* ar = As + (lrow + p * 64) * GST + s0;
        ar[0] = f2tf(pa[p].x); ar[2] = f2tf(pa[p].y);
        ar[4] = f2tf(pa[p].z); ar[6] = f2tf(pa[p].w);
        uint32_t* br = Bs + (lrow + p * 64) * GST + s0;
        br[0] = f2tf(pw[p].x); br[2] = f2tf(pw[p].y);
        br[4] = f2tf(pw[p].z); br[6] = f2tf(pw[p].w);
    }

    const int NIT = DMODEL / 16;   // 48
    for (int it = 0; it < NIT; it++) {
        __syncthreads();
        if (it + 1 < NIT) {
            const int k0 = (it + 1) << 4;
            #pragma unroll
            for (int p = 0; p < 2; p++) {
                pa[p] = *(const float4*)(A + (size_t)(m0 + lrow + p * 64) * DMODEL + k0 + lc4);
                pw[p] = *(const float4*)(W + (size_t)(n0 + lrow + p * 64) * DMODEL + k0 + lc4);
            }
        }
        const uint32_t* ab = As + (it & 1) * G_BUF;
        const uint32_t* bb = Bs + (it & 1) * G_BUF;
        #pragma unroll
        for (int ks = 0; ks < 2; ks++) {
            const int kb8 = ks * 8 + 2 * q;
            uint2 aA[2][2];
            #pragma unroll
            for (int im = 0; im < 2; im++) {
                const int mr = wm * 32 + im * 16 + g;
                aA[im][0] = *(const uint2*)&ab[mr * GST + kb8];
                aA[im][1] = *(const uint2*)&ab[(mr + 8) * GST + kb8];
            }
            #pragma unroll
            for (int j = 0; j < 8; j++) {
                uint2 bu = *(const uint2*)&bb[(wn * 64 + j * 8 + g) * GST + kb8];
                mma8(acc[0][j], aA[0][0].x, aA[0][1].x, aA[0][0].y, aA[0][1].y, bu.x, bu.y);
                mma8(acc[1][j], aA[1][0].x, aA[1][1].x, aA[1][0].y, aA[1][1].y, bu.x, bu.y);
            }
        }
        if (it + 1 < NIT) {
            uint32_t* aw = As + ((it + 1) & 1) * G_BUF;
            uint32_t* bw = Bs + ((it + 1) & 1) * G_BUF;
            #pragma unroll
            for (int p = 0; p < 2; p++) {
                uint32_t* ar = aw + (lrow + p * 64) * GST + s0;
                ar[0] = f2tf(pa[p].x); ar[2] = f2tf(pa[p].y);
                ar[4] = f2tf(pa[p].z); ar[6] = f2tf(pa[p].w);
                uint32_t* br = bw + (lrow + p * 64) * GST + s0;
                br[0] = f2tf(pw[p].x); br[2] = f2tf(pw[p].y);
                br[4] = f2tf(pw[p].z); br[6] = f2tf(pw[p].w);
            }
        }
    }

    #pragma unroll
    for (int im = 0; im < 2; im++) {
        const int row0 = m0 + wm * 32 + im * 16 + g;
        #pragma unroll
        for (int j = 0; j < 8; j++) {
            const int col = n0 + wn * 64 + j * 8 + 2 * q;
            const float b0v = bias[col], b1v = bias[col + 1];
            float2 o0, o1;
            o0.x = acc[im][j][0] + b0v; o0.y = acc[im][j][1] + b1v;
            o1.x = acc[im][j][2] + b0v; o1.y = acc[im][j][3] + b1v;
            if (permute) {
                const int h = col >> 6, d = col & 63;
                const int bi0 = row0 >> 11, sr0 = row0 & (SLEN - 1);
                *(float2*)(C + (((size_t)(bi0 * HEADS + h) * SLEN) + sr0) * DK + d) = o0;
                const int row1 = row0 + 8;
                const int bi1 = row1 >> 11, sr1 = row1 & (SLEN - 1);
                *(float2*)(C + (((size_t)(bi1 * HEADS + h) * SLEN) + sr1) * DK + d) = o1;
            } else {
                *(float2*)(C + (size_t)row0 * DMODEL + col) = o0;
                *(float2*)(C + (size_t)(row0 + 8) * DMODEL + col) = o1;
            }
        }
    }
}

// ---------------------------------------------------------------------------
// Flash attention, tf32 mma.sync. Block = 128 q rows, 128 threads (4 warps),
// each warp owns 32 rows (two m16 fragments) -> every K/V fragment load feeds
// 2 MMAs (1.5 LDS.32 per MMA instead of 2.5).
// ---------------------------------------------------------------------------
#define QST 68
#define VST 72
#define AOFF_K 8704            // 128*68 (Q)
#define AOFF_V 13056           // + 64*68 (K)
#define AOFF_P 17664           // + 64*72 (V)
#define A_SM_WORDS 26368       // + 128*68 (P: 4 warps x 32 rows)
#define A_SM_BYTES (A_SM_WORDS * 4)

__global__ __launch_bounds__(128) void attn_tf32(
    const float* __restrict__ qh, const float* __restrict__ kh,
    const float* __restrict__ vh, float* __restrict__ concat)
{
    extern __shared__ uint32_t sma[];
    uint32_t* Qs = sma;
    uint32_t* Ks = sma + AOFF_K;
    uint32_t* Vs = sma + AOFF_V;
    uint32_t* Ps = sma + AOFF_P;

    const int tid  = threadIdx.x;
    const int lane = tid & 31;
    const int w    = tid >> 5;
    const int g = lane >> 2, q = lane & 3;
    const int qt = blockIdx.x, bh = blockIdx.y;
    const int b = bh / HEADS, h = bh % HEADS;

    const float* Qp = qh + ((size_t)bh * SLEN + qt * 128) * DK;
    const float* Kp = kh + (size_t)bh * SLEN * DK;
    const float* Vp = vh + (size_t)bh * SLEN * DK;

    // Stage Q (scaled by 1/8 = 1/sqrt(Dk), exact)
    #pragma unroll
    for (int p = 0; p < 16; p++) {
        const int idx = tid + p * 128;
        const int row = idx >> 4, c4 = (idx & 15) << 2;
        float4 v = *(const float4*)(Qp + row * DK + c4);
        uint4 u;
        u.x = f2tf(v.x * 0.125f); u.y = f2tf(v.y * 0.125f);
        u.z = f2tf(v.z * 0.125f); u.w = f2tf(v.w * 0.125f);
        *(uint4*)(Qs + row * QST + c4) = u;
    }

    float O[2][8][4];
    float mr[2][2], lr[2][2];
    #pragma unroll
    for (int im = 0; im < 2; im++) {
        mr[im][0] = -1e30f; mr[im][1] = -1e30f;
        lr[im][0] = 0.f;    lr[im][1] = 0.f;
        #pragma unroll
        for (int j = 0; j < 8; j++)
            #pragma unroll
            for (int t = 0; t < 4; t++) O[im][j][t] = 0.f;
    }

    uint32_t* Pw = Ps + w * 32 * QST;
    const int mb = w * 32;

    for (int kt = 0; kt < SLEN / 64; kt++) {
        __syncthreads();
        const float* kb = Kp + (size_t)kt * 64 * DK;
        const float* vb = Vp + (size_t)kt * 64 * DK;
        #pragma unroll
        for (int p = 0; p < 8; p++) {
            const int idx = tid + p * 128;
            const int row = idx >> 4, c4 = (idx & 15) << 2;
            float4 kv = *(const float4*)(kb + row * DK + c4);
            uint4 ku;
            ku.x = f2tf(kv.x); ku.y = f2tf(kv.y); ku.z = f2tf(kv.z); ku.w = f2tf(kv.w);
            *(uint4*)(Ks + row * QST + c4) = ku;
            float4 vv = *(const float4*)(vb + row * DK + c4);
            uint4 vu;
            vu.x = f2tf(vv.x); vu.y = f2tf(vv.y); vu.z = f2tf(vv.z); vu.w = f2tf(vv.w);
            *(uint4*)(Vs + row * VST + c4) = vu;
        }
        __syncthreads();

        // S = (Q/8) @ K^T : two m-frags per warp share each K fragment
        float S[2][8][4];
        #pragma unroll
        for (int im = 0; im < 2; im++)
            #pragma unroll
            for (int j = 0; j < 8; j++)
                #pragma unroll
                for (int t = 0; t < 4; t++) S[im][j][t] = 0.f;
        #pragma unroll
        for (int ks = 0; ks < 8; ks++) {
            const int kk = ks * 8;
            uint32_t a[2][4];
            #pragma unroll
            for (int im = 0; im < 2; im++) {
                const int rb = mb + im * 16;
                a[im][0] = Qs[(rb + g) * QST + kk + q];
                a[im][1] = Qs[(rb + g + 8) * QST + kk + q];
                a[im][2] = Qs[(rb + g) * QST + kk + q + 4];
                a[im][3] = Qs[(rb + g + 8) * QST + kk + q + 4];
            }
            #pragma unroll
            for (int j = 0; j < 8; j++) {
                uint32_t b0 = Ks[(j * 8 + g) * QST + kk + q];
                uint32_t b1 = Ks[(j * 8 + g) * QST + kk + q + 4];
                mma8(S[0][j], a[0][0], a[0][1], a[0][2], a[0][3], b0, b1);
                mma8(S[1][j], a[1][0], a[1][1], a[1][2], a[1][3], b0, b1);
            }
        }

        // Online softmax per m-frag (rows on quad lanes -> shfl xor 1,2)
        #pragma unroll
        for (int im = 0; im < 2; im++) {
            float mx0 = -1e30f, mx1 = -1e30f;
            #pragma unroll
            for (int j = 0; j < 8; j++) {
                mx0 = fmaxf(mx0, fmaxf(S[im][j][0], S[im][j][1]));
                mx1 = fmaxf(mx1, fmaxf(S[im][j][2], S[im][j][3]));
            }
            mx0 = fmaxf(mx0, __shfl_xor_sync(0xffffffffu, mx0, 1));
            mx0 = fmaxf(mx0, __shfl_xor_sync(0xffffffffu, mx0, 2));
            mx1 = fmaxf(mx1, __shfl_xor_sync(0xffffffffu, mx1, 1));
            mx1 = fmaxf(mx1, __shfl_xor_sync(0xffffffffu, mx1, 2));

            const float nm0 = fmaxf(mr[im][0], mx0), nm1 = fmaxf(mr[im][1], mx1);
            const float f0 = __expf(mr[im][0] - nm0), f1 = __expf(mr[im][1] - nm1);
            mr[im][0] = nm0; mr[im][1] = nm1;

            float sm0 = 0.f, sm1 = 0.f;
            const int rb = im * 16;
            #pragma unroll
            for (int j = 0; j < 8; j++) {
                const float e0 = __expf(S[im][j][0] - nm0);
                const float e1 = __expf(S[im][j][1] - nm0);
                const float e2 = __expf(S[im][j][2] - nm1);
                const float e3 = __expf(S[im][j][3] - nm1);
                sm0 += e0 + e1; sm1 += e2 + e3;
                uint2 p01, p23;
                p01.x = f2tf(e0); p01.y = f2tf(e1);
                p23.x = f2tf(e2); p23.y = f2tf(e3);
                *(uint2*)(Pw + (rb + g) * QST + j * 8 + 2 * q) = p01;
                *(uint2*)(Pw + (rb + g + 8) * QST + j * 8 + 2 * q) = p23;
            }
            sm0 += __shfl_xor_sync(0xffffffffu, sm0, 1);
            sm0 += __shfl_xor_sync(0xffffffffu, sm0, 2);
            sm1 += __shfl_xor_sync(0xffffffffu, sm1, 1);
            sm1 += __shfl_xor_sync(0xffffffffu, sm1, 2);
            lr[im][0] = lr[im][0] * f0 + sm0;
            lr[im][1] = lr[im][1] * f1 + sm1;
            #pragma unroll
            for (int j = 0; j < 8; j++) {
                O[im][j][0] *= f0; O[im][j][1] *= f0;
                O[im][j][2] *= f1; O[im][j][3] *= f1;
            }
        }
        __syncwarp();

        // O += P @ V : V fragments shared across the two m-frags
        #pragma unroll
        for (int ks = 0; ks < 8; ks++) {
            const int kk = ks * 8;
            uint32_t a[2][4];
            #pragma unroll
            for (int im = 0; im < 2; im++) {
                const int rb = im * 16;
                a[im][0] = Pw[(rb + g) * QST + kk + q];
                a[im][1] = Pw[(rb + g + 8) * QST + kk + q];
                a[im][2] = Pw[(rb + g) * QST + kk + q + 4];
                a[im][3] = Pw[(rb + g + 8) * QST + kk + q + 4];
            }
            #pragma unroll
            for (int j = 0; j < 8; j++) {
                uint32_t b0 = Vs[(kk + q) * VST + j * 8 + g];
                uint32_t b1 = Vs[(kk + q + 4) * VST + j * 8 + g];
                mma8(O[0][j], a[0][0], a[0][1], a[0][2], a[0][3], b0, b1);
                mma8(O[1][j], a[1][0], a[1][1], a[1][2], a[1][3], b0, b1);
            }
        }
    }

    // Normalize + write concat [b][s][h*64+d]
    #pragma unroll
    for (int im = 0; im < 2; im++) {
        const float inv0 = 1.f / lr[im][0], inv1 = 1.f / lr[im][1];
        const int srow = qt * 128 + w * 32 + im * 16 + g;
        const size_t base0 = ((size_t)b * SLEN + srow) * DMODEL + h * 64;
        const size_t base1 = base0 + (size_t)8 * DMODEL;
        #pragma unroll
        for (int j = 0; j < 8; j++) {
            float2 o0, o1;
            o0.x = O[im][j][0] * inv0; o0.y = O[im][j][1] * inv0;
            o1.x = O[im][j][2] * inv1; o1.y = O[im][j][3] * inv1;
            *(float2*)(concat + base0 + j * 8 + 2 * q) = o0;
            *(float2*)(concat + base1 + j * 8 + 2 * q) = o1;
        }
    }
}

// ---------------------------------------------------------------------------
extern "C" void kernel_launch(void* const* d_in, const int* in_sizes, int n_in,
                              void* d_out, int out_size)
{
    (void)in_sizes; (void)n_in; (void)out_size;
    const float* q  = (const float*)d_in[0];
    const float* k  = (const float*)d_in[1];
    const float* v  = (const float*)d_in[2];
    const float* Wk = (const float*)d_in[3];
    const float* bk = (const float*)d_in[4];
    const float* Wo = (const float*)d_in[5];
    const float* bo = (const float*)d_in[6];
    float* out = (float*)d_out;

    float *qh, *kh, *vh, *concat;
    cudaGetSymbolAddress((void**)&qh, g_qh);
    cudaGetSymbolAddress((void**)&kh, g_kh);
    cudaGetSymbolAddress((void**)&vh, g_vh);
    cudaGetSymbolAddress((void**)&concat, g_concat);

    cudaFuncSetAttribute((const void*)gemm_tf32,
                         cudaFuncAttributeMaxDynamicSharedMemorySize, G_SMEM_BYTES);
    cudaFuncSetAttribute((const void*)attn_tf32,
                         cudaFuncAttributeMaxDynamicSharedMemorySize, A_SM_BYTES);

    dim3 gp(DMODEL / 128, MTOT / 128, 3);   // fused q/k/v projections
    gemm_tf32<<<gp, 256, G_SMEM_BYTES>>>(q, k, v, qh, kh, vh, Wk, bk, 1);

    attn_tf32<<<dim3(SLEN / 128, BATCH * HEADS), 128, A_SM_BYTES>>>(qh, kh, vh, concat);

    dim3 go(DMODEL / 128, MTOT / 128, 1);
    gemm_tf32<<<go, 256, G_SMEM_BYTES>>>(concat, concat, concat, out, out, out, Wo, bo, 0);
}

// round 7
// speedup vs baseline: 1.2544x; 1.0014x over previous
#include <cuda_runtime.h>
#include <stdint.h>
#include <math.h>

#define HEADS  12
#define DMODEL 768
#define DK     64
#define BATCH  2
#define SLEN   2048
#define MTOT   (BATCH * SLEN)   // 4096

__device__ float g_qh[BATCH * HEADS * SLEN * DK];
__device__ float g_kh[BATCH * HEADS * SLEN * DK];
__device__ float g_vh[BATCH * HEADS * SLEN * DK];
__device__ float g_concat[MTOT * DMODEL];

// ---------------------------------------------------------------------------
__device__ __forceinline__ uint32_t f2tf(float x) {
    uint32_t r;
    asm("cvt.rna.tf32.f32 %0, %1;" : "=r"(r) : "f"(x));
    return r;
}

__device__ __forceinline__ void mma8(float* c,
    uint32_t a0, uint32_t a1, uint32_t a2, uint32_t a3,
    uint32_t b0, uint32_t b1)
{
    asm volatile(
        "mma.sync.aligned.m16n8k8.row.col.f32.tf32.tf32.f32 "
        "{%0,%1,%2,%3},{%4,%5,%6,%7},{%8,%9},{%0,%1,%2,%3};"
        : "+f"(c[0]), "+f"(c[1]), "+f"(c[2]), "+f"(c[3])
        : "r"(a0), "r"(a1), "r"(a2), "r"(a3), "r"(b0), "r"(b1));
}

// ---------------------------------------------------------------------------
// GEMM (R3-proven): C = A @ W^T + bias, double-buffered smem, pair-interleaved
// k layout (LDS.64 frag loads). Block 128x128, BK=16, 8 warps (4m x 2n).
// blockIdx.z selects (A,C). permute -> [B,H,S,Dk] store.
// ---------------------------------------------------------------------------
#define GST 24                  // row stride in words (16 k + pad)
#define G_BUF (128 * GST)       // words per operand per buffer
#define G_SMEM_BYTES (4 * G_BUF * 4)   // 49152 B

__global__ __launch_bounds__(256) void gemm_tf32(
    const float* __restrict__ A0, const float* __restrict__ A1,
    const float* __restrict__ A2,
    float* __restrict__ C0, float* __restrict__ C1, float* __restrict__ C2,
    const float* __restrict__ W, const float* __restrict__ bias, int permute)
{
    extern __shared__ uint32_t gsm[];
    uint32_t* As = gsm;               // [2][128*GST]
    uint32_t* Bs = gsm + 2 * G_BUF;   // [2][128*GST]

    const float* A = (blockIdx.z == 0) ? A0 : (blockIdx.z == 1) ? A1 : A2;
    float*       C = (blockIdx.z == 0) ? C0 : (blockIdx.z == 1) ? C1 : C2;

    const int tid  = threadIdx.x;
    const int lane = tid & 31;
    const int wid  = tid >> 5;
    const int g = lane >> 2, q = lane & 3;
    const int wm = wid >> 1, wn = wid & 1;
    const int m0 = blockIdx.y << 7, n0 = blockIdx.x << 7;
    const int lrow = tid >> 2;           // 0..63
    const int lc4  = (tid & 3) << 2;     // 0,4,8,12
    const int s0   = (lc4 & 8) + ((lc4 >> 2) & 1);  // interleave start slot

    float acc[2][8][4];
    #pragma unroll
    for (int im = 0; im < 2; im++)
        #pragma unroll
        for (int j = 0; j < 8; j++)
            #pragma unroll
            for (int t = 0; t < 4; t++) acc[im][j][t] = 0.f;

    float4 pa[2], pw[2];
    #pragma unroll
    for (int p = 0; p < 2; p++) {
        pa[p] = *(const float4*)(A + (size_t)(m0 + lrow + p * 64) * DMODEL + lc4);
        pw[p] = *(const float4*)(W + (size_t)(n0 + lrow + p * 64) * DMODEL + lc4);
    }
    #pragma unroll
    for (int p = 0; p < 2; p++) {
        uint32_t* ar = As + (lrow + p * 64) * GST + s0;
        ar[0] = f2tf(pa[p].x); ar[2] = f2tf(pa[p].y);
        ar[4] = f2tf(pa[p].z); ar[6] = f2tf(pa[p].w);
        uint32_t* br = Bs + (lrow + p * 64) * GST + s0;
        br[0] = f2tf(pw[p].x); br[2] = f2tf(pw[p].y);
        br[4] = f2tf(pw[p].z); br[6] = f2tf(pw[p].w);
    }

    const int NIT = DMODEL / 16;   // 48
    for (int it = 0; it < NIT; it++) {
        __syncthreads();
        if (it + 1 < NIT) {
            const int k0 = (it + 1) << 4;
            #pragma unroll
            for (int p = 0; p < 2; p++) {
                pa[p] = *(const float4*)(A + (size_t)(m0 + lrow + p * 64) * DMODEL + k0 + lc4);
                pw[p] = *(const float4*)(W + (size_t)(n0 + lrow + p * 64) * DMODEL + k0 + lc4);
            }
        }
        const uint32_t* ab = As + (it & 1) * G_BUF;
        const uint32_t* bb = Bs + (it & 1) * G_BUF;
        #pragma unroll
        for (int ks = 0; ks < 2; ks++) {
            const int kb8 = ks * 8 + 2 * q;
            uint2 aA[2][2];
            #pragma unroll
            for (int im = 0; im < 2; im++) {
                const int mr = wm * 32 + im * 16 + g;
                aA[im][0] = *(const uint2*)&ab[mr * GST + kb8];
                aA[im][1] = *(const uint2*)&ab[(mr + 8) * GST + kb8];
            }
            #pragma unroll
            for (int j = 0; j < 8; j++) {
                uint2 bu = *(const uint2*)&bb[(wn * 64 + j * 8 + g) * GST + kb8];
                mma8(acc[0][j], aA[0][0].x, aA[0][1].x, aA[0][0].y, aA[0][1].y, bu.x, bu.y);
                mma8(acc[1][j], aA[1][0].x, aA[1][1].x, aA[1][0].y, aA[1][1].y, bu.x, bu.y);
            }
        }
        if (it + 1 < NIT) {
            uint32_t* aw = As + ((it + 1) & 1) * G_BUF;
            uint32_t* bw = Bs + ((it + 1) & 1) * G_BUF;
            #pragma unroll
            for (int p = 0; p < 2; p++) {
                uint32_t* ar = aw + (lrow + p * 64) * GST + s0;
                ar[0] = f2tf(pa[p].x); ar[2] = f2tf(pa[p].y);
                ar[4] = f2tf(pa[p].z); ar[6] = f2tf(pa[p].w);
                uint32_t* br = bw + (lrow + p * 64) * GST + s0;
                br[0] = f2tf(pw[p].x); br[2] = f2tf(pw[p].y);
                br[4] = f2tf(pw[p].z); br[6] = f2tf(pw[p].w);
            }
        }
    }

    #pragma unroll
    for (int im = 0; im < 2; im++) {
        const int row0 = m0 + wm * 32 + im * 16 + g;
        #pragma unroll
        for (int j = 0; j < 8; j++) {
            const int col = n0 + wn * 64 + j * 8 + 2 * q;
            const float b0v = bias[col], b1v = bias[col + 1];
            float2 o0, o1;
            o0.x = acc[im][j][0] + b0v; o0.y = acc[im][j][1] + b1v;
            o1.x = acc[im][j][2] + b0v; o1.y = acc[im][j][3] + b1v;
            if (permute) {
                const int h = col >> 6, d = col & 63;
                const int bi0 = row0 >> 11, sr0 = row0 & (SLEN - 1);
                *(float2*)(C + (((size_t)(bi0 * HEADS + h) * SLEN) + sr0) * DK + d) = o0;
                const int row1 = row0 + 8;
                const int bi1 = row1 >> 11, sr1 = row1 & (SLEN - 1);
                *(float2*)(C + (((size_t)(bi1 * HEADS + h) * SLEN) + sr1) * DK + d) = o1;
            } else {
                *(float2*)(C + (size_t)row0 * DMODEL + col) = o0;
                *(float2*)(C + (size_t)(row0 + 8) * DMODEL + col) = o1;
            }
        }
    }
}

// ---------------------------------------------------------------------------
// Flash attention, tf32 mma.sync. Block = 128 q rows, 128 threads (4 warps),
// each warp owns 32 rows (two m16 fragments) -> every K/V fragment load feeds
// 2 MMAs (1.5 LDS.32 per MMA instead of 2.5).
// ---------------------------------------------------------------------------
#define QST 68
#define VST 72
#define AOFF_K 8704            // 128*68 (Q)
#define AOFF_V 13056           // + 64*68 (K)
#define AOFF_P 17664           // + 64*72 (V)
#define A_SM_WORDS 26368       // + 128*68 (P: 4 warps x 32 rows)
#define A_SM_BYTES (A_SM_WORDS * 4)

__global__ __launch_bounds__(128) void attn_tf32(
    const float* __restrict__ qh, const float* __restrict__ kh,
    const float* __restrict__ vh, float* __restrict__ concat)
{
    extern __shared__ uint32_t sma[];
    uint32_t* Qs = sma;
    uint32_t* Ks = sma + AOFF_K;
    uint32_t* Vs = sma + AOFF_V;
    uint32_t* Ps = sma + AOFF_P;

    const int tid  = threadIdx.x;
    const int lane = tid & 31;
    const int w    = tid >> 5;
    const int g = lane >> 2, q = lane & 3;
    const int qt = blockIdx.x, bh = blockIdx.y;
    const int b = bh / HEADS, h = bh % HEADS;

    const float* Qp = qh + ((size_t)bh * SLEN + qt * 128) * DK;
    const float* Kp = kh + (size_t)bh * SLEN * DK;
    const float* Vp = vh + (size_t)bh * SLEN * DK;

    // Stage Q (scaled by 1/8 = 1/sqrt(Dk), exact)
    #pragma unroll
    for (int p = 0; p < 16; p++) {
        const int idx = tid + p * 128;
        const int row = idx >> 4, c4 = (idx & 15) << 2;
        float4 v = *(const float4*)(Qp + row * DK + c4);
        uint4 u;
        u.x = f2tf(v.x * 0.125f); u.y = f2tf(v.y * 0.125f);
        u.z = f2tf(v.z * 0.125f); u.w = f2tf(v.w * 0.125f);
        *(uint4*)(Qs + row * QST + c4) = u;
    }

    float O[2][8][4];
    float mr[2][2], lr[2][2];
    #pragma unroll
    for (int im = 0; im < 2; im++) {
        mr[im][0] = -1e30f; mr[im][1] = -1e30f;
        lr[im][0] = 0.f;    lr[im][1] = 0.f;
        #pragma unroll
        for (int j = 0; j < 8; j++)
            #pragma unroll
            for (int t = 0; t < 4; t++) O[im][j][t] = 0.f;
    }

    uint32_t* Pw = Ps + w * 32 * QST;
    const int mb = w * 32;

    for (int kt = 0; kt < SLEN / 64; kt++) {
        __syncthreads();
        const float* kb = Kp + (size_t)kt * 64 * DK;
        const float* vb = Vp + (size_t)kt * 64 * DK;
        #pragma unroll
        for (int p = 0; p < 8; p++) {
            const int idx = tid + p * 128;
            const int row = idx >> 4, c4 = (idx & 15) << 2;
            float4 kv = *(const float4*)(kb + row * DK + c4);
            uint4 ku;
            ku.x = f2tf(kv.x); ku.y = f2tf(kv.y); ku.z = f2tf(kv.z); ku.w = f2tf(kv.w);
            *(uint4*)(Ks + row * QST + c4) = ku;
            float4 vv = *(const float4*)(vb + row * DK + c4);
            uint4 vu;
            vu.x = f2tf(vv.x); vu.y = f2tf(vv.y); vu.z = f2tf(vv.z); vu.w = f2tf(vv.w);
            *(uint4*)(Vs + row * VST + c4) = vu;
        }
        __syncthreads();

        // S = (Q/8) @ K^T : two m-frags per warp share each K fragment
        float S[2][8][4];
        #pragma unroll
        for (int im = 0; im < 2; im++)
            #pragma unroll
            for (int j = 0; j < 8; j++)
                #pragma unroll
                for (int t = 0; t < 4; t++) S[im][j][t] = 0.f;
        #pragma unroll
        for (int ks = 0; ks < 8; ks++) {
            const int kk = ks * 8;
            uint32_t a[2][4];
            #pragma unroll
            for (int im = 0; im < 2; im++) {
                const int rb = mb + im * 16;
                a[im][0] = Qs[(rb + g) * QST + kk + q];
                a[im][1] = Qs[(rb + g + 8) * QST + kk + q];
                a[im][2] = Qs[(rb + g) * QST + kk + q + 4];
                a[im][3] = Qs[(rb + g + 8) * QST + kk + q + 4];
            }
            #pragma unroll
            for (int j = 0; j < 8; j++) {
                uint32_t b0 = Ks[(j * 8 + g) * QST + kk + q];
                uint32_t b1 = Ks[(j * 8 + g) * QST + kk + q + 4];
                mma8(S[0][j], a[0][0], a[0][1], a[0][2], a[0][3], b0, b1);
                mma8(S[1][j], a[1][0], a[1][1], a[1][2], a[1][3], b0, b1);
            }
        }

        // Online softmax per m-frag (rows on quad lanes -> shfl xor 1,2)
        #pragma unroll
        for (int im = 0; im < 2; im++) {
            float mx0 = -1e30f, mx1 = -1e30f;
            #pragma unroll
            for (int j = 0; j < 8; j++) {
                mx0 = fmaxf(mx0, fmaxf(S[im][j][0], S[im][j][1]));
                mx1 = fmaxf(mx1, fmaxf(S[im][j][2], S[im][j][3]));
            }
            mx0 = fmaxf(mx0, __shfl_xor_sync(0xffffffffu, mx0, 1));
            mx0 = fmaxf(mx0, __shfl_xor_sync(0xffffffffu, mx0, 2));
            mx1 = fmaxf(mx1, __shfl_xor_sync(0xffffffffu, mx1, 1));
            mx1 = fmaxf(mx1, __shfl_xor_sync(0xffffffffu, mx1, 2));

            const float nm0 = fmaxf(mr[im][0], mx0), nm1 = fmaxf(mr[im][1], mx1);
            const float f0 = __expf(mr[im][0] - nm0), f1 = __expf(mr[im][1] - nm1);
            mr[im][0] = nm0; mr[im][1] = nm1;

            float sm0 = 0.f, sm1 = 0.f;
            const int rb = im * 16;
            #pragma unroll
            for (int j = 0; j < 8; j++) {
                const float e0 = __expf(S[im][j][0] - nm0);
                const float e1 = __expf(S[im][j][1] - nm0);
                const float e2 = __expf(S[im][j][2] - nm1);
                const float e3 = __expf(S[im][j][3] - nm1);
                sm0 += e0 + e1; sm1 += e2 + e3;
                uint2 p01, p23;
                p01.x = f2tf(e0); p01.y = f2tf(e1);
                p23.x = f2tf(e2); p23.y = f2tf(e3);
                *(uint2*)(Pw + (rb + g) * QST + j * 8 + 2 * q) = p01;
                *(uint2*)(Pw + (rb + g + 8) * QST + j * 8 + 2 * q) = p23;
            }
            sm0 += __shfl_xor_sync(0xffffffffu, sm0, 1);
            sm0 += __shfl_xor_sync(0xffffffffu, sm0, 2);
            sm1 += __shfl_xor_sync(0xffffffffu, sm1, 1);
            sm1 += __shfl_xor_sync(0xffffffffu, sm1, 2);
            lr[im][0] = lr[im][0] * f0 + sm0;
            lr[im][1] = lr[im][1] * f1 + sm1;
            #pragma unroll
            for (int j = 0; j < 8; j++) {
                O[im][j][0] *= f0; O[im][j][1] *= f0;
                O[im][j][2] *= f1; O[im][j][3] *= f1;
            }
        }
        __syncwarp();

        // O += P @ V : V fragments shared across the two m-frags
        #pragma unroll
        for (int ks = 0; ks < 8; ks++) {
            const int kk = ks * 8;
            uint32_t a[2][4];
            #pragma unroll
            for (int im = 0; im < 2; im++) {
                const int rb = im * 16;
                a[im][0] = Pw[(rb + g) * QST + kk + q];
                a[im][1] = Pw[(rb + g + 8) * QST + kk + q];
                a[im][2] = Pw[(rb + g) * QST + kk + q + 4];
                a[im][3] = Pw[(rb + g + 8) * QST + kk + q + 4];
            }
            #pragma unroll
            for (int j = 0; j < 8; j++) {
                uint32_t b0 = Vs[(kk + q) * VST + j * 8 + g];
                uint32_t b1 = Vs[(kk + q + 4) * VST + j * 8 + g];
                mma8(O[0][j], a[0][0], a[0][1], a[0][2], a[0][3], b0, b1);
                mma8(O[1][j], a[1][0], a[1][1], a[1][2], a[1][3], b0, b1);
            }
        }
    }

    // Normalize + write concat [b][s][h*64+d]
    #pragma unroll
    for (int im = 0; im < 2; im++) {
        const float inv0 = 1.f / lr[im][0], inv1 = 1.f / lr[im][1];
        const int srow = qt * 128 + w * 32 + im * 16 + g;
        const size_t base0 = ((size_t)b * SLEN + srow) * DMODEL + h * 64;
        const size_t base1 = base0 + (size_t)8 * DMODEL;
        #pragma unroll
        for (int j = 0; j < 8; j++) {
            float2 o0, o1;
            o0.x = O[im][j][0] * inv0; o0.y = O[im][j][1] * inv0;
            o1.x = O[im][j][2] * inv1; o1.y = O[im][j][3] * inv1;
            *(float2*)(concat + base0 + j * 8 + 2 * q) = o0;
            *(float2*)(concat + base1 + j * 8 + 2 * q) = o1;
        }
    }
}

// ---------------------------------------------------------------------------
extern "C" void kernel_launch(void* const* d_in, const int* in_sizes, int n_in,
                              void* d_out, int out_size)
{
    (void)in_sizes; (void)n_in; (void)out_size;
    const float* q  = (const float*)d_in[0];
    const float* k  = (const float*)d_in[1];
    const float* v  = (const float*)d_in[2];
    const float* Wk = (const float*)d_in[3];
    const float* bk = (const float*)d_in[4];
    const float* Wo = (const float*)d_in[5];
    const float* bo = (const float*)d_in[6];
    float* out = (float*)d_out;

    float *qh, *kh, *vh, *concat;
    cudaGetSymbolAddress((void**)&qh, g_qh);
    cudaGetSymbolAddress((void**)&kh, g_kh);
    cudaGetSymbolAddress((void**)&vh, g_vh);
    cudaGetSymbolAddress((void**)&concat, g_concat);

    cudaFuncSetAttribute((const void*)gemm_tf32,
                         cudaFuncAttributeMaxDynamicSharedMemorySize, G_SMEM_BYTES);
    cudaFuncSetAttribute((const void*)attn_tf32,
                         cudaFuncAttributeMaxDynamicSharedMemorySize, A_SM_BYTES);

    dim3 gp(DMODEL / 128, MTOT / 128, 3);   // fused q/k/v projections
    gemm_tf32<<<gp, 256, G_SMEM_BYTES>>>(q, k, v, qh, kh, vh, Wk, bk, 1);

    attn_tf32<<<dim3(SLEN / 128, BATCH * HEADS), 128, A_SM_BYTES>>>(qh, kh, vh, concat);

    dim3 go(DMODEL / 128, MTOT / 128, 1);
    gemm_tf32<<<go, 256, G_SMEM_BYTES>>>(concat, concat, concat, out, out, out, Wo, bo, 0);
}

// round 8
// speedup vs baseline: 1.3606x; 1.0846x over previous
#include <cuda_runtime.h>
#include <stdint.h>
#include <math.h>

#define HEADS  12
#define DMODEL 768
#define DK     64
#define BATCH  2
#define SLEN   2048
#define MTOT   (BATCH * SLEN)   // 4096

__device__ float g_qh[BATCH * HEADS * SLEN * DK];
__device__ float g_kh[BATCH * HEADS * SLEN * DK];
__device__ float g_vh[BATCH * HEADS * SLEN * DK];
__device__ float g_concat[MTOT * DMODEL];

// ---------------------------------------------------------------------------
__device__ __forceinline__ uint32_t f2tf(float x) {
    uint32_t r;
    asm("cvt.rna.tf32.f32 %0, %1;" : "=r"(r) : "f"(x));
    return r;
}

__device__ __forceinline__ void mma8(float* c,
    uint32_t a0, uint32_t a1, uint32_t a2, uint32_t a3,
    uint32_t b0, uint32_t b1)
{
    asm volatile(
        "mma.sync.aligned.m16n8k8.row.col.f32.tf32.tf32.f32 "
        "{%0,%1,%2,%3},{%4,%5,%6,%7},{%8,%9},{%0,%1,%2,%3};"
        : "+f"(c[0]), "+f"(c[1]), "+f"(c[2]), "+f"(c[3])
        : "r"(a0), "r"(a1), "r"(a2), "r"(a3), "r"(b0), "r"(b1));
}

__device__ __forceinline__ uint32_t smem_u32(const void* p) {
    uint32_t a;
    asm("{ .reg .u64 t; cvta.to.shared.u64 t, %1; cvt.u32.u64 %0, t; }"
        : "=r"(a) : "l"(p));
    return a;
}

#define CPA16(d, s) \
    asm volatile("cp.async.cg.shared.global [%0], [%1], 16;" :: "r"(d), "l"(s))
#define CPA_COMMIT() asm volatile("cp.async.commit_group;" ::: "memory")
#define CPA_WAIT1()  asm volatile("cp.async.wait_group 1;" ::: "memory")
#define CPA_WAIT0()  asm volatile("cp.async.wait_group 0;" ::: "memory")

// ---------------------------------------------------------------------------
// GEMM (R3-proven): C = A @ W^T + bias, double-buffered smem, pair-interleaved
// k layout. Block 128x128, BK=16, 8 warps (4m x 2n).
// permute: outputs for attention are written tf32-PRE-ROUNDED; qh additionally
// pre-scaled by 1/8 = 1/sqrt(Dk) (exact, commutes with rounding).
// ---------------------------------------------------------------------------
#define GST 24
#define G_BUF (128 * GST)
#define G_SMEM_BYTES (4 * G_BUF * 4)   // 49152 B

__global__ __launch_bounds__(256) void gemm_tf32(
    const float* __restrict__ A0, const float* __restrict__ A1,
    const float* __restrict__ A2,
    float* __restrict__ C0, float* __restrict__ C1, float* __restrict__ C2,
    const float* __restrict__ W, const float* __restrict__ bias, int permute)
{
    extern __shared__ uint32_t gsm[];
    uint32_t* As = gsm;
    uint32_t* Bs = gsm + 2 * G_BUF;

    const float* A = (blockIdx.z == 0) ? A0 : (blockIdx.z == 1) ? A1 : A2;
    float*       C = (blockIdx.z == 0) ? C0 : (blockIdx.z == 1) ? C1 : C2;

    const int tid  = threadIdx.x;
    const int lane = tid & 31;
    const int wid  = tid >> 5;
    const int g = lane >> 2, q = lane & 3;
    const int wm = wid >> 1, wn = wid & 1;
    const int m0 = blockIdx.y << 7, n0 = blockIdx.x << 7;
    const int lrow = tid >> 2;
    const int lc4  = (tid & 3) << 2;
    const int s0   = (lc4 & 8) + ((lc4 >> 2) & 1);

    float acc[2][8][4];
    #pragma unroll
    for (int im = 0; im < 2; im++)
        #pragma unroll
        for (int j = 0; j < 8; j++)
            #pragma unroll
            for (int t = 0; t < 4; t++) acc[im][j][t] = 0.f;

    float4 pa[2], pw[2];
    #pragma unroll
    for (int p = 0; p < 2; p++) {
        pa[p] = *(const float4*)(A + (size_t)(m0 + lrow + p * 64) * DMODEL + lc4);
        pw[p] = *(const float4*)(W + (size_t)(n0 + lrow + p * 64) * DMODEL + lc4);
    }
    #pragma unroll
    for (int p = 0; p < 2; p++) {
        uint32_t* ar = As + (lrow + p * 64) * GST + s0;
        ar[0] = f2tf(pa[p].x); ar[2] = f2tf(pa[p].y);
        ar[4] = f2tf(pa[p].z); ar[6] = f2tf(pa[p].w);
        uint32_t* br = Bs + (lrow + p * 64) * GST + s0;
        br[0] = f2tf(pw[p].x); br[2] = f2tf(pw[p].y);
        br[4] = f2tf(pw[p].z); br[6] = f2tf(pw[p].w);
    }

    const int NIT = DMODEL / 16;   // 48
    for (int it = 0; it < NIT; it++) {
        __syncthreads();
        if (it + 1 < NIT) {
            const int k0 = (it + 1) << 4;
            #pragma unroll
            for (int p = 0; p < 2; p++) {
                pa[p] = *(const float4*)(A + (size_t)(m0 + lrow + p * 64) * DMODEL + k0 + lc4);
                pw[p] = *(const float4*)(W + (size_t)(n0 + lrow + p * 64) * DMODEL + k0 + lc4);
            }
        }
        const uint32_t* ab = As + (it & 1) * G_BUF;
        const uint32_t* bb = Bs + (it & 1) * G_BUF;
        #pragma unroll
        for (int ks = 0; ks < 2; ks++) {
            const int kb8 = ks * 8 + 2 * q;
            uint2 aA[2][2];
            #pragma unroll
            for (int im = 0; im < 2; im++) {
                const int mr = wm * 32 + im * 16 + g;
                aA[im][0] = *(const uint2*)&ab[mr * GST + kb8];
                aA[im][1] = *(const uint2*)&ab[(mr + 8) * GST + kb8];
            }
            #pragma unroll
            for (int j = 0; j < 8; j++) {
                uint2 bu = *(const uint2*)&bb[(wn * 64 + j * 8 + g) * GST + kb8];
                mma8(acc[0][j], aA[0][0].x, aA[0][1].x, aA[0][0].y, aA[0][1].y, bu.x, bu.y);
                mma8(acc[1][j], aA[1][0].x, aA[1][1].x, aA[1][0].y, aA[1][1].y, bu.x, bu.y);
            }
        }
        if (it + 1 < NIT) {
            uint32_t* aw = As + ((it + 1) & 1) * G_BUF;
            uint32_t* bw = Bs + ((it + 1) & 1) * G_BUF;
            #pragma unroll
            for (int p = 0; p < 2; p++) {
                uint32_t* ar = aw + (lrow + p * 64) * GST + s0;
                ar[0] = f2tf(pa[p].x); ar[2] = f2tf(pa[p].y);
                ar[4] = f2tf(pa[p].z); ar[6] = f2tf(pa[p].w);
                uint32_t* br = bw + (lrow + p * 64) * GST + s0;
                br[0] = f2tf(pw[p].x); br[2] = f2tf(pw[p].y);
                br[4] = f2tf(pw[p].z); br[6] = f2tf(pw[p].w);
            }
        }
    }

    // Epilogue. permute path: pre-round to tf32 (qh also pre-scaled by 1/8).
    const float scl = (permute && blockIdx.z == 0) ? 0.125f : 1.0f;
    #pragma unroll
    for (int im = 0; im < 2; im++) {
        const int row0 = m0 + wm * 32 + im * 16 + g;
        #pragma unroll
        for (int j = 0; j < 8; j++) {
            const int col = n0 + wn * 64 + j * 8 + 2 * q;
            const float b0v = bias[col], b1v = bias[col + 1];
            float2 o0, o1;
            o0.x = acc[im][j][0] + b0v; o0.y = acc[im][j][1] + b1v;
            o1.x = acc[im][j][2] + b0v; o1.y = acc[im][j][3] + b1v;
            if (permute) {
                o0.x = __uint_as_float(f2tf(o0.x * scl));
                o0.y = __uint_as_float(f2tf(o0.y * scl));
                o1.x = __uint_as_float(f2tf(o1.x * scl));
                o1.y = __uint_as_float(f2tf(o1.y * scl));
                const int h = col >> 6, d = col & 63;
                const int bi0 = row0 >> 11, sr0 = row0 & (SLEN - 1);
                *(float2*)(C + (((size_t)(bi0 * HEADS + h) * SLEN) + sr0) * DK + d) = o0;
                const int row1 = row0 + 8;
                const int bi1 = row1 >> 11, sr1 = row1 & (SLEN - 1);
                *(float2*)(C + (((size_t)(bi1 * HEADS + h) * SLEN) + sr1) * DK + d) = o1;
            } else {
                *(float2*)(C + (size_t)row0 * DMODEL + col) = o0;
                *(float2*)(C + (size_t)(row0 + 8) * DMODEL + col) = o1;
            }
        }
    }
}

// ---------------------------------------------------------------------------
// Flash attention: 128 q-rows/CTA, 128 threads (4 warps x 32 rows).
// Operands arrive pre-rounded tf32 -> cp.async staging, no cvt.
// Q fragments in registers (Q smem region reused as P). K/V double-buffered.
// ---------------------------------------------------------------------------
#define QST 68
#define VST 72
#define W_QP 0                       // 128*68 = 8704 words: Q stage, then P
#define W_K0 8704                    // 64*68 = 4352
#define W_K1 (W_K0 + 4352)
#define W_V0 (W_K1 + 4352)           // 64*72 = 4608
#define W_V1 (W_V0 + 4608)
#define A_WORDS (W_V1 + 4608)        // 26624
#define A_SM_BYTES (A_WORDS * 4)     // 106496

__global__ __launch_bounds__(128) void attn_tf32(
    const float* __restrict__ qh, const float* __restrict__ kh,
    const float* __restrict__ vh, float* __restrict__ concat)
{
    extern __shared__ uint32_t sma[];
    const uint32_t sb = smem_u32(sma);

    const int tid  = threadIdx.x;
    const int lane = tid & 31;
    const int w    = tid >> 5;
    const int g = lane >> 2, q = lane & 3;
    const int qt = blockIdx.x, bh = blockIdx.y;
    const int b = bh / HEADS, h = bh % HEADS;

    const float* Qp = qh + ((size_t)bh * SLEN + qt * 128) * DK;
    const float* Kp = kh + (size_t)bh * SLEN * DK;
    const float* Vp = vh + (size_t)bh * SLEN * DK;

    // Stage Q (already tf32-rounded and 1/8-scaled)
    #pragma unroll
    for (int p = 0; p < 16; p++) {
        const int idx = tid + p * 128;
        const int row = idx >> 4, cc = (idx & 15) << 2;
        CPA16(sb + (W_QP + row * QST + cc) * 4, Qp + row * DK + cc);
    }
    CPA_COMMIT();
    // KV tile 0
    #pragma unroll
    for (int p = 0; p < 8; p++) {
        const int idx = tid + p * 128;
        const int row = idx >> 4, cc = (idx & 15) << 2;
        CPA16(sb + (W_K0 + row * QST + cc) * 4, Kp + row * DK + cc);
        CPA16(sb + (W_V0 + row * VST + cc) * 4, Vp + row * DK + cc);
    }
    CPA_COMMIT();

    CPA_WAIT1();          // Q group complete (KV0 may still be in flight)
    __syncthreads();

    // Q fragments -> registers (held for the whole kernel)
    uint32_t qf[2][8][4];
    #pragma unroll
    for (int im = 0; im < 2; im++) {
        const int rb = w * 32 + im * 16;
        #pragma unroll
        for (int ks = 0; ks < 8; ks++) {
            const int kk = ks * 8;
            qf[im][ks][0] = sma[W_QP + (rb + g) * QST + kk + q];
            qf[im][ks][1] = sma[W_QP + (rb + g + 8) * QST + kk + q];
            qf[im][ks][2] = sma[W_QP + (rb + g) * QST + kk + q + 4];
            qf[im][ks][3] = sma[W_QP + (rb + g + 8) * QST + kk + q + 4];
        }
    }
    __syncthreads();      // all warps done reading Q; region becomes P

    float O[2][8][4];
    float mr[2][2], lr[2][2];
    #pragma unroll
    for (int im = 0; im < 2; im++) {
        mr[im][0] = -1e30f; mr[im][1] = -1e30f;
        lr[im][0] = 0.f;    lr[im][1] = 0.f;
        #pragma unroll
        for (int j = 0; j < 8; j++)
            #pragma unroll
            for (int t = 0; t < 4; t++) O[im][j][t] = 0.f;
    }

    uint32_t* Pw = sma + W_QP + w * 32 * QST;

    for (int kt = 0; kt < SLEN / 64; kt++) {
        // Prefetch next KV tile into the other buffer
        if (kt + 1 < SLEN / 64) {
            const float* kb = Kp + (size_t)(kt + 1) * 64 * DK;
            const float* vb = Vp + (size_t)(kt + 1) * 64 * DK;
            const int wk = ((kt + 1) & 1) ? W_K1 : W_K0;
            const int wv = ((kt + 1) & 1) ? W_V1 : W_V0;
            #pragma unroll
            for (int p = 0; p < 8; p++) {
                const int idx = tid + p * 128;
                const int row = idx >> 4, cc = (idx & 15) << 2;
                CPA16(sb + (wk + row * QST + cc) * 4, kb + row * DK + cc);
                CPA16(sb + (wv + row * VST + cc) * 4, vb + row * DK + cc);
            }
            CPA_COMMIT();
            CPA_WAIT1();   // current tile's group done; next stays in flight
        } else {
            CPA_WAIT0();
        }
        __syncthreads();

        const uint32_t* Ksb = sma + ((kt & 1) ? W_K1 : W_K0);
        const uint32_t* Vsb = sma + ((kt & 1) ? W_V1 : W_V0);

        // S = (Q/8) @ K^T : K fragments shared across both m-frags
        float S[2][8][4];
        #pragma unroll
        for (int im = 0; im < 2; im++)
            #pragma unroll
            for (int j = 0; j < 8; j++)
                #pragma unroll
                for (int t = 0; t < 4; t++) S[im][j][t] = 0.f;
        #pragma unroll
        for (int ks = 0; ks < 8; ks++) {
            const int kk = ks * 8;
            #pragma unroll
            for (int j = 0; j < 8; j++) {
                uint32_t b0 = Ksb[(j * 8 + g) * QST + kk + q];
                uint32_t b1 = Ksb[(j * 8 + g) * QST + kk + q + 4];
                mma8(S[0][j], qf[0][ks][0], qf[0][ks][1], qf[0][ks][2], qf[0][ks][3], b0, b1);
                mma8(S[1][j], qf[1][ks][0], qf[1][ks][1], qf[1][ks][2], qf[1][ks][3], b0, b1);
            }
        }

        // Online softmax per m-frag (rows on quad lanes -> shfl xor 1,2)
        #pragma unroll
        for (int im = 0; im < 2; im++) {
            float mx0 = -1e30f, mx1 = -1e30f;
            #pragma unroll
            for (int j = 0; j < 8; j++) {
                mx0 = fmaxf(mx0, fmaxf(S[im][j][0], S[im][j][1]));
                mx1 = fmaxf(mx1, fmaxf(S[im][j][2], S[im][j][3]));
            }
            mx0 = fmaxf(mx0, __shfl_xor_sync(0xffffffffu, mx0, 1));
            mx0 = fmaxf(mx0, __shfl_xor_sync(0xffffffffu, mx0, 2));
            mx1 = fmaxf(mx1, __shfl_xor_sync(0xffffffffu, mx1, 1));
            mx1 = fmaxf(mx1, __shfl_xor_sync(0xffffffffu, mx1, 2));

            const float nm0 = fmaxf(mr[im][0], mx0), nm1 = fmaxf(mr[im][1], mx1);
            const float f0 = __expf(mr[im][0] - nm0), f1 = __expf(mr[im][1] - nm1);
            mr[im][0] = nm0; mr[im][1] = nm1;

            float sm0 = 0.f, sm1 = 0.f;
            const int rb = im * 16;
            #pragma unroll
            for (int j = 0; j < 8; j++) {
                const float e0 = __expf(S[im][j][0] - nm0);
                const float e1 = __expf(S[im][j][1] - nm0);
                const float e2 = __expf(S[im][j][2] - nm1);
                const float e3 = __expf(S[im][j][3] - nm1);
                sm0 += e0 + e1; sm1 += e2 + e3;
                uint2 p01, p23;
                p01.x = f2tf(e0); p01.y = f2tf(e1);
                p23.x = f2tf(e2); p23.y = f2tf(e3);
                *(uint2*)(Pw + (rb + g) * QST + j * 8 + 2 * q) = p01;
                *(uint2*)(Pw + (rb + g + 8) * QST + j * 8 + 2 * q) = p23;
            }
            sm0 += __shfl_xor_sync(0xffffffffu, sm0, 1);
            sm0 += __shfl_xor_sync(0xffffffffu, sm0, 2);
            sm1 += __shfl_xor_sync(0xffffffffu, sm1, 1);
            sm1 += __shfl_xor_sync(0xffffffffu, sm1, 2);
            lr[im][0] = lr[im][0] * f0 + sm0;
            lr[im][1] = lr[im][1] * f1 + sm1;
            #pragma unroll
            for (int j = 0; j < 8; j++) {
                O[im][j][0] *= f0; O[im][j][1] *= f0;
                O[im][j][2] *= f1; O[im][j][3] *= f1;
            }
        }
        __syncwarp();

        // O += P @ V : V fragments shared across both m-frags
        #pragma unroll
        for (int ks = 0; ks < 8; ks++) {
            const int kk = ks * 8;
            uint32_t a[2][4];
            #pragma unroll
            for (int im = 0; im < 2; im++) {
                const int rb = im * 16;
                a[im][0] = Pw[(rb + g) * QST + kk + q];
                a[im][1] = Pw[(rb + g + 8) * QST + kk + q];
                a[im][2] = Pw[(rb + g) * QST + kk + q + 4];
                a[im][3] = Pw[(rb + g + 8) * QST + kk + q + 4];
            }
            #pragma unroll
            for (int j = 0; j < 8; j++) {
                uint32_t b0 = Vsb[(kk + q) * VST + j * 8 + g];
                uint32_t b1 = Vsb[(kk + q + 4) * VST + j * 8 + g];
                mma8(O[0][j], a[0][0], a[0][1], a[0][2], a[0][3], b0, b1);
                mma8(O[1][j], a[1][0], a[1][1], a[1][2], a[1][3], b0, b1);
            }
        }
        __syncthreads();   // protect KV buffers before next prefetch overwrites
    }

    // Normalize + write concat [b][s][h*64+d]
    #pragma unroll
    for (int im = 0; im < 2; im++) {
        const float inv0 = 1.f / lr[im][0], inv1 = 1.f / lr[im][1];
        const int srow = qt * 128 + w * 32 + im * 16 + g;
        const size_t base0 = ((size_t)b * SLEN + srow) * DMODEL + h * 64;
        const size_t base1 = base0 + (size_t)8 * DMODEL;
        #pragma unroll
        for (int j = 0; j < 8; j++) {
            float2 o0, o1;
            o0.x = O[im][j][0] * inv0; o0.y = O[im][j][1] * inv0;
            o1.x = O[im][j][2] * inv1; o1.y = O[im][j][3] * inv1;
            *(float2*)(concat + base0 + j * 8 + 2 * q) = o0;
            *(float2*)(concat + base1 + j * 8 + 2 * q) = o1;
        }
    }
}

// ---------------------------------------------------------------------------
extern "C" void kernel_launch(void* const* d_in, const int* in_sizes, int n_in,
                              void* d_out, int out_size)
{
    (void)in_sizes; (void)n_in; (void)out_size;
    const float* q  = (const float*)d_in[0];
    const float* k  = (const float*)d_in[1];
    const float* v  = (const float*)d_in[2];
    const float* Wk = (const float*)d_in[3];
    const float* bk = (const float*)d_in[4];
    const float* Wo = (const float*)d_in[5];
    const float* bo = (const float*)d_in[6];
    float* out = (float*)d_out;

    float *qh, *kh, *vh, *concat;
    cudaGetSymbolAddress((void**)&qh, g_qh);
    cudaGetSymbolAddress((void**)&kh, g_kh);
    cudaGetSymbolAddress((void**)&vh, g_vh);
    cudaGetSymbolAddress((void**)&concat, g_concat);

    cudaFuncSetAttribute((const void*)gemm_tf32,
                         cudaFuncAttributeMaxDynamicSharedMemorySize, G_SMEM_BYTES);
    cudaFuncSetAttribute((const void*)attn_tf32,
                         cudaFuncAttributeMaxDynamicSharedMemorySize, A_SM_BYTES);

    dim3 gp(DMODEL / 128, MTOT / 128, 3);   // fused q/k/v projections
    gemm_tf32<<<gp, 256, G_SMEM_BYTES>>>(q, k, v, qh, kh, vh, Wk, bk, 1);

    attn_tf32<<<dim3(SLEN / 128, BATCH * HEADS), 128, A_SM_BYTES>>>(qh, kh, vh, concat);

    dim3 go(DMODEL / 128, MTOT / 128, 1);
    gemm_tf32<<<go, 256, G_SMEM_BYTES>>>(concat, concat, concat, out, out, out, Wo, bo, 0);
}